// round 9
// baseline (speedup 1.0000x reference)
#include <cuda_runtime.h>
#include <cstddef>

#define T_STEPS 512
#define BATCH   64
#define HID     512
#define GATES   2048
#define NLAYER  2
#define MROWS   (T_STEPS * BATCH)   // 32768
#define NB      128                 // persistent CTAs
#define NGRP    4                   // independent batch groups
#define GRP_CTAS 32                 // CTAs per group
#define HDEPTH  4                   // h ring depth

// ---------------- device scratch (static allocation — allowed) ----------------
__device__ float g_xw[(size_t)MROWS * GATES];            // 256 MB input projection
__device__ float g_seq1[(size_t)T_STEPS * BATCH * HID];  // 64 MB layer-0 output
__device__ float g_hT[HDEPTH * NGRP * HID * 16];         // transposed h ring
__device__ float g_wpT[(size_t)NLAYER * HID * GATES];    // packed W_hh [l][k][gate][u]

// monotonic step-completion counters: one 32B-slot per (grp, ring slot),
// separate 128B line per group
__device__ unsigned g_cnt3[NGRP * 32];
// end-of-kernel election counters, parity-alternating across launches
__device__ unsigned g_fin[2 * NGRP * 32];

// ---------------- f32x2 helpers ------------------------------------------------
__device__ __forceinline__ unsigned long long pk2(float lo, float hi) {
    unsigned long long r;
    asm("mov.b64 %0, {%1, %2};" : "=l"(r) : "f"(lo), "f"(hi));
    return r;
}
__device__ __forceinline__ unsigned long long ffma2(
    unsigned long long a, unsigned long long b, unsigned long long c) {
    unsigned long long d;
    asm("fma.rn.f32x2 %0, %1, %2, %3;" : "=l"(d) : "l"(a), "l"(b), "l"(c));
    return d;
}
__device__ __forceinline__ void unpk2(unsigned long long v, float& lo, float& hi) {
    asm("mov.b64 {%0, %1}, %2;" : "=f"(lo), "=f"(hi) : "l"(v));
}

// ---------------- pack W_hh into [k][gate][u] ----------------------------------
__global__ void pack_whh(const float* __restrict__ W_hh)
{
    int idx = blockIdx.x * 256 + threadIdx.x;
    int l = idx / (HID * GATES);
    int r = idx - l * (HID * GATES);
    int k    = r >> 11;
    int q    = r & 2047;
    int gate = q >> 9;
    int u    = q & 511;
    g_wpT[idx] = W_hh[((size_t)l * GATES + gate * HID + u) * HID + k];
}

// ---------------- SGEMM: C[M,2048] = A[M,512]*W[2048,512]^T + (bih+bhh) --------
// (unchanged from R8 — double-buffered, proven)
__global__ void __launch_bounds__(256) gemm_bias(
    const float* __restrict__ A,
    const float* __restrict__ W,
    const float* __restrict__ bih,
    const float* __restrict__ bhh,
    float* __restrict__ C)
{
    __shared__ __align__(16) float As[2][16][128];
    __shared__ __align__(16) float Bs[2][16][128];

    int tid = threadIdx.x;
    int bx = blockIdx.x;
    int by = blockIdx.y;
    int tm = tid >> 4;
    int tn = tid & 15;

    unsigned long long acc2[8][4];
#pragma unroll
    for (int i = 0; i < 8; i++)
#pragma unroll
        for (int p = 0; p < 4; p++) acc2[i][p] = 0ull;

    const int rowA = by * 128;
    const int rowW = bx * 128;

#define LOAD_TILE(k0, s)                                                      \
    {                                                                         \
        _Pragma("unroll")                                                     \
        for (int r = 0; r < 2; r++) {                                         \
            int v  = tid + r * 256;                                           \
            int rr = v >> 2;                                                  \
            int kq = v & 3;                                                   \
            float4 av = *(const float4*)&A[(size_t)(rowA + rr) * HID + (k0) + kq * 4]; \
            As[s][kq * 4 + 0][rr] = av.x; As[s][kq * 4 + 1][rr] = av.y;       \
            As[s][kq * 4 + 2][rr] = av.z; As[s][kq * 4 + 3][rr] = av.w;       \
            float4 wv = *(const float4*)&W[(size_t)(rowW + rr) * HID + (k0) + kq * 4]; \
            Bs[s][kq * 4 + 0][rr] = wv.x; Bs[s][kq * 4 + 1][rr] = wv.y;       \
            Bs[s][kq * 4 + 2][rr] = wv.z; Bs[s][kq * 4 + 3][rr] = wv.w;       \
        }                                                                     \
    }

    LOAD_TILE(0, 0)

    for (int it = 0; it < 32; it++) {
        __syncthreads();
        int s = it & 1;
        if (it + 1 < 32) LOAD_TILE((it + 1) * 16, s ^ 1)
#pragma unroll
        for (int kk = 0; kk < 16; kk++) {
            float a[8];
            float4 t0 = *(const float4*)&As[s][kk][tm * 8];
            float4 t1 = *(const float4*)&As[s][kk][tm * 8 + 4];
            a[0]=t0.x; a[1]=t0.y; a[2]=t0.z; a[3]=t0.w;
            a[4]=t1.x; a[5]=t1.y; a[6]=t1.z; a[7]=t1.w;
            float4 s0 = *(const float4*)&Bs[s][kk][tn * 8];
            float4 s1 = *(const float4*)&Bs[s][kk][tn * 8 + 4];
            unsigned long long bp[4];
            bp[0] = pk2(s0.x, s0.y); bp[1] = pk2(s0.z, s0.w);
            bp[2] = pk2(s1.x, s1.y); bp[3] = pk2(s1.z, s1.w);
#pragma unroll
            for (int i = 0; i < 8; i++) {
                unsigned long long ai = pk2(a[i], a[i]);
#pragma unroll
                for (int p = 0; p < 4; p++)
                    acc2[i][p] = ffma2(ai, bp[p], acc2[i][p]);
            }
        }
    }
#undef LOAD_TILE

    int n0 = rowW + tn * 8;
    float bias[8];
#pragma unroll
    for (int j = 0; j < 8; j++) bias[j] = bih[n0 + j] + bhh[n0 + j];
#pragma unroll
    for (int i = 0; i < 8; i++) {
        float v[8];
#pragma unroll
        for (int p = 0; p < 4; p++) unpk2(acc2[i][p], v[2*p], v[2*p+1]);
        size_t off = (size_t)(rowA + tm * 8 + i) * GATES + n0;
        float4 o0 = make_float4(v[0] + bias[0], v[1] + bias[1],
                                v[2] + bias[2], v[3] + bias[3]);
        float4 o1 = make_float4(v[4] + bias[4], v[5] + bias[5],
                                v[6] + bias[6], v[7] + bias[7]);
        *(float4*)&C[off]     = o0;
        *(float4*)&C[off + 4] = o1;
    }
}

// ---------------- persistent recurrence ----------------------------------------
// 128 CTAs = 32 u-tiles (16 units) x 4 b-groups (16 batches). 256 threads.
// Sync: monotonic per-(grp, slot) counters. Producer: one red.release.add after
// h(t) stored. Consumer: warps spin (lane 0) on ld.acquire until all 32 CTAs
// posted h(t-1). h ring depth 4: a CTA writing h(t+4) to slot t%4 has observed
// count(t+3)=32, which implies every CTA completed stage(t+1) -- the only read
// of slot t%4 -- so the overwrite is safe. CTAs drift instead of lock-stepping.
// Compute chains + reduction order bitwise identical to R8.
__global__ void __launch_bounds__(256, 1) lstm_seq(
    const float* __restrict__ wpT,    // layer's packed W_hh [k][gate][u]
    const float* __restrict__ xw,     // [T][BATCH][GATES]
    float* __restrict__ hT,           // [HDEPTH][NGRP][HID][16]
    float* __restrict__ ybase,        // [T][BATCH][HID]
    float* __restrict__ hs_out,
    float* __restrict__ cs_out,
    int seq)                          // launch sequence parity (0/1)
{
    extern __shared__ __align__(16) float smem[];
    float* Wsh = smem;                      // [512][64]       128 KB
    float* Hsh = smem + 32768;              // [512][20]        40 KB
    float* Psh = smem + 32768 + 10240;      // [8][64][18]      36 KB

    const int tid  = threadIdx.x;
    const int warp = tid >> 5;          // k-chunk 0..7
    const int lane = tid & 31;
    const int utile = blockIdx.x & 31;
    const int grp   = blockIdx.x >> 5;
    const int u0 = utile * 16;
    const int b0 = grp * 16;
    const int uu = tid & 15;            // update role
    const int bb = tid >> 4;            // batch 0..15
    const int gidx = (b0 + bb) * HID + u0 + uu;
    const int kbase = warp * 64;

    unsigned* cnt = &g_cnt3[grp * 32];  // slot s at cnt[s*8]

    // ---- load this CTA's W_hh slice into smem once: Wsh[k*64 + g*16 + u] ----
    for (int i = tid; i < 512 * 64; i += 256) {
        int luu = i & 15;
        int lg  = (i >> 4) & 3;
        int lk  = i >> 6;
        Wsh[i] = wpT[(size_t)lk * GATES + lg * HID + u0 + luu];
    }
    __syncthreads();

    float c = 0.f;

    // prefetch xw(0)
    {
        const float* xp = xw + ((size_t)(b0 + bb)) * GATES + u0 + uu;
        float x0 = xp[0], x1 = xp[512], x2 = xp[1024], x3 = xp[1536];

#pragma unroll 1
        for (int t = 0; t < T_STEPS; t++) {
            float pre0 = x0, pre1 = x1, pre2 = x2, pre3 = x3;
            if (t > 0) {
                const int slot = (t - 1) & 3;
                const unsigned target = 32u * ((unsigned)((t - 1) >> 2) + 1u);
                // ---- per-warp wait: all 32 CTAs posted h(t-1) ---------------
                if (lane == 0) {
                    unsigned v;
                    do {
                        asm volatile("ld.acquire.gpu.global.u32 %0, [%1];"
                                     : "=r"(v) : "l"(cnt + slot * 8) : "memory");
                    } while (v < target);
                }
                __syncwarp();

                // ---- per-warp stage of OWN chunk: LDG.128(cg) -> STS.128 ----
                const float4* src = (const float4*)(hT +
                    (size_t)(slot * NGRP + grp) * HID * 16);
                const int base4 = kbase * 4;
#pragma unroll
                for (int i = 0; i < 8; i++) {
                    int idx = base4 + lane + i * 32;
                    float4 v = __ldcg(src + idx);
                    int k  = idx >> 2;
                    int ch = idx & 3;
                    *(float4*)&Hsh[k * 20 + ch * 4] = v;
                }
                __syncwarp();

                // ---- compute: rows {2l,2l+1} x 16 b over 64 consecutive k ---
                unsigned long long acc2[2][8];
#pragma unroll
                for (int r = 0; r < 2; r++)
#pragma unroll
                    for (int i = 0; i < 8; i++) acc2[r][i] = 0ull;

#pragma unroll 8
                for (int j = 0; j < 64; j++) {
                    int k = kbase + j;
                    const float* hr = &Hsh[k * 20];
                    ulonglong2 q0 = *(const ulonglong2*)(hr + 0);
                    ulonglong2 q1 = *(const ulonglong2*)(hr + 4);
                    ulonglong2 q2 = *(const ulonglong2*)(hr + 8);
                    ulonglong2 q3 = *(const ulonglong2*)(hr + 12);
                    float2 wv = *(const float2*)&Wsh[k * 64 + 2 * lane];
                    unsigned long long w0 = pk2(wv.x, wv.x);
                    unsigned long long w1 = pk2(wv.y, wv.y);
                    acc2[0][0] = ffma2(w0, q0.x, acc2[0][0]);
                    acc2[0][1] = ffma2(w0, q0.y, acc2[0][1]);
                    acc2[0][2] = ffma2(w0, q1.x, acc2[0][2]);
                    acc2[0][3] = ffma2(w0, q1.y, acc2[0][3]);
                    acc2[0][4] = ffma2(w0, q2.x, acc2[0][4]);
                    acc2[0][5] = ffma2(w0, q2.y, acc2[0][5]);
                    acc2[0][6] = ffma2(w0, q3.x, acc2[0][6]);
                    acc2[0][7] = ffma2(w0, q3.y, acc2[0][7]);
                    acc2[1][0] = ffma2(w1, q0.x, acc2[1][0]);
                    acc2[1][1] = ffma2(w1, q0.y, acc2[1][1]);
                    acc2[1][2] = ffma2(w1, q1.x, acc2[1][2]);
                    acc2[1][3] = ffma2(w1, q1.y, acc2[1][3]);
                    acc2[1][4] = ffma2(w1, q2.x, acc2[1][4]);
                    acc2[1][5] = ffma2(w1, q2.y, acc2[1][5]);
                    acc2[1][6] = ffma2(w1, q3.x, acc2[1][6]);
                    acc2[1][7] = ffma2(w1, q3.y, acc2[1][7]);
                }

                // ---- write partials --------------------------------------------
#pragma unroll
                for (int r = 0; r < 2; r++) {
                    int base = warp * 1152 + (2 * lane + r) * 18;
#pragma unroll
                    for (int i = 0; i < 8; i++)
                        *(unsigned long long*)&Psh[base + 2 * i] = acc2[r][i];
                }
                __syncthreads();

                // ---- fixed-order reduction: chunks 0..7 ascending, + xw last ---
                float s0 = Psh[(0 * 16 + uu) * 18 + bb];
                float s1 = Psh[(1 * 16 + uu) * 18 + bb];
                float s2 = Psh[(2 * 16 + uu) * 18 + bb];
                float s3 = Psh[(3 * 16 + uu) * 18 + bb];
#pragma unroll
                for (int cc = 1; cc < 8; cc++) {
                    int base = cc * 1152 + uu * 18 + bb;
                    s0 += Psh[base];
                    s1 += Psh[base + 16 * 18];
                    s2 += Psh[base + 32 * 18];
                    s3 += Psh[base + 48 * 18];
                }
                pre0 = s0 + x0; pre1 = s1 + x1;
                pre2 = s2 + x2; pre3 = s3 + x3;
            }

            {
                float i_ = pre0 >= 0.f ? 1.f : 0.f;
                float f_ = pre1 >= 0.f ? 1.f : 0.f;
                float gg = pre2 >= 0.f ? 1.f : 0.f;
                float o_ = pre3 >= 0.f ? 1.f : 0.f;

                c = c * f_ + i_ * gg;
                float h = c * o_;

                __stcg(&ybase[(size_t)t * BATCH * HID + gidx], h);
                __stcg(&hT[(size_t)((t & 3) * NGRP + grp) * HID * 16
                           + (u0 + uu) * 16 + bb], h);
                if (t == T_STEPS - 1) {
                    hs_out[gidx] = h;
                    cs_out[gidx] = c;
                }
            }
            __syncthreads();           // all h(t) stores issued
            if (tid == 0) {
                asm volatile("red.release.gpu.global.add.u32 [%0], 1;"
                             :: "l"(cnt + (t & 3) * 8) : "memory");
            }

            // prefetch xw(t+1): latency hides under next step's spin
            if (t + 1 < T_STEPS) {
                const float* xr = xw + ((size_t)(t + 1) * BATCH + b0 + bb) * GATES
                                     + u0 + uu;
                x0 = xr[0]; x1 = xr[512]; x2 = xr[1024]; x3 = xr[1536];
            }
        }
    }

    // ---- end-of-kernel: elect last CTA of group, reset counters --------------
    // Parity-alternating fin counters: this launch arrives on g_fin[seq&1];
    // the elected resetter zeroes the step counters AND the OTHER parity's fin
    // (whose users are all long gone), preparing it for the next launch.
    __syncthreads();
    if (tid == 0) {
        unsigned* fin   = &g_fin[((seq & 1) * NGRP + grp) * 32];
        unsigned* fin_o = &g_fin[(((seq & 1) ^ 1) * NGRP + grp) * 32];
        unsigned old;
        asm volatile("atom.acq_rel.gpu.global.add.u32 %0, [%1], 1;"
                     : "=r"(old) : "l"(fin) : "memory");
        if (old == GRP_CTAS - 1u) {
            // all 32 CTAs of the group fully done: nobody touches cnt again
#pragma unroll
            for (int s = 0; s < 4; s++)
                asm volatile("st.relaxed.gpu.global.u32 [%0], 0;"
                             :: "l"(cnt + s * 8) : "memory");
            asm volatile("st.relaxed.gpu.global.u32 [%0], 0;"
                         :: "l"(fin_o) : "memory");
        }
    }
}

// ---------------- launch --------------------------------------------------------
extern "C" void kernel_launch(void* const* d_in, const int* in_sizes, int n_in,
                              void* d_out, int out_size)
{
    (void)in_sizes; (void)n_in; (void)out_size;
    const float* x    = (const float*)d_in[0];
    const float* W_ih = (const float*)d_in[1];
    const float* W_hh = (const float*)d_in[2];
    const float* b_ih = (const float*)d_in[3];
    const float* b_hh = (const float*)d_in[4];
    float* out = (float*)d_out;

    float *xw, *seq1, *hT, *wpT;
    cudaGetSymbolAddress((void**)&xw,   g_xw);
    cudaGetSymbolAddress((void**)&seq1, g_seq1);
    cudaGetSymbolAddress((void**)&hT,   g_hT);
    cudaGetSymbolAddress((void**)&wpT,  g_wpT);

    const int SMEM_BYTES = (32768 + 10240 + 9216) * 4;   // 208896
    cudaFuncSetAttribute(lstm_seq, cudaFuncAttributeMaxDynamicSharedMemorySize,
                         SMEM_BYTES);

    pack_whh<<<(NLAYER * HID * GATES) / 256, 256>>>(W_hh);

    const size_t TBH = (size_t)T_STEPS * BATCH * HID;

    for (int l = 0; l < NLAYER; l++) {
        const float* A = (l == 0) ? x : seq1;
        gemm_bias<<<dim3(GATES / 128, MROWS / 128), 256>>>(
            A, W_ih + (size_t)l * GATES * HID,
            b_ih + (size_t)l * GATES, b_hh + (size_t)l * GATES, xw);

        float* ybase = (l == 0) ? seq1 : out;
        float* hs = out + TBH + (size_t)l * BATCH * HID;
        float* cs = out + TBH + (size_t)NLAYER * BATCH * HID + (size_t)l * BATCH * HID;

        lstm_seq<<<NB, 256, SMEM_BYTES>>>(wpT + (size_t)l * HID * GATES,
                                          xw, hT, ybase, hs, cs, l);
    }
}

// round 10
// speedup vs baseline: 1.0512x; 1.0512x over previous
#include <cuda_runtime.h>
#include <cstddef>

#define T_STEPS 512
#define BATCH   64
#define HID     512
#define GATES   2048
#define NLAYER  2
#define MROWS   (T_STEPS * BATCH)   // 32768
#define NB      128                 // persistent CTAs
#define NGRP    4                   // independent batch groups
#define GRP_CTAS 32                 // CTAs per group

// ---------------- device scratch (static allocation — allowed) ----------------
__device__ float g_xw[(size_t)MROWS * GATES];            // 256 MB input projection
__device__ float g_seq1[(size_t)T_STEPS * BATCH * HID];  // 64 MB layer-0 output
__device__ float g_hT[2 * NGRP * HID * 16];              // transposed h [buf][grp][u][b]
__device__ float g_wpT[(size_t)NLAYER * HID * GATES];    // packed W_hh [l][k][gate][u]

// tree barrier state: 4 sub lines + 1 super line + 1 sense line per group
__device__ unsigned g_sub[NGRP * 4 * 32];
__device__ unsigned g_sup[NGRP * 32];
__device__ unsigned g_sns[NGRP * 32];
// one-shot global barrier (prologue), double-flip per launch -> self-restoring
__device__ unsigned g_gcnt[32];
__device__ unsigned g_gsns[32];

// ---------------- f32x2 helpers ------------------------------------------------
__device__ __forceinline__ unsigned long long pk2(float lo, float hi) {
    unsigned long long r;
    asm("mov.b64 %0, {%1, %2};" : "=l"(r) : "f"(lo), "f"(hi));
    return r;
}
__device__ __forceinline__ unsigned long long ffma2(
    unsigned long long a, unsigned long long b, unsigned long long c) {
    unsigned long long d;
    asm("fma.rn.f32x2 %0, %1, %2, %3;" : "=l"(d) : "l"(a), "l"(b), "l"(c));
    return d;
}
__device__ __forceinline__ void unpk2(unsigned long long v, float& lo, float& hi) {
    asm("mov.b64 {%0, %1}, %2;" : "=f"(lo), "=f"(hi) : "l"(v));
}

// ---------------- pack W_hh into [k][gate][u] ----------------------------------
__global__ void pack_whh(const float* __restrict__ W_hh)
{
    int idx = blockIdx.x * 256 + threadIdx.x;
    int l = idx / (HID * GATES);
    int r = idx - l * (HID * GATES);
    int k    = r >> 11;
    int q    = r & 2047;
    int gate = q >> 9;
    int u    = q & 511;
    g_wpT[idx] = W_hh[((size_t)l * GATES + gate * HID + u) * HID + k];
}

// ---------------- barriers ------------------------------------------------------
// global (128 CTAs), centralized; MUST be called an even number of times/launch
__device__ __forceinline__ void gbar(unsigned& sense)
{
    __syncthreads();
    unsigned s = sense ^ 1u;
    sense = s;
    if (threadIdx.x == 0) {
        unsigned old;
        asm volatile("atom.acq_rel.gpu.global.add.u32 %0, [%1], 1;"
                     : "=r"(old) : "l"(&g_gcnt[0]) : "memory");
        if (old == NB - 1u) {
            asm volatile("st.relaxed.gpu.global.u32 [%0], 0;"
                         :: "l"(&g_gcnt[0]) : "memory");
            asm volatile("st.release.gpu.global.u32 [%0], %1;"
                         :: "l"(&g_gsns[0]), "r"(s) : "memory");
        } else {
            unsigned v;
            do {
                asm volatile("ld.acquire.gpu.global.u32 %0, [%1];"
                             : "=r"(v) : "l"(&g_gsns[0]) : "memory");
            } while (v != s);
        }
    }
    __syncthreads();
}

// per-group tree-arrive barrier: 4 sub-counters (8 CTAs each) -> super -> sense.
// Single spinner per CTA (tid 0) on one sense word (the R8-proven shape).
__device__ __forceinline__ void group_bar(int grp, int subi, unsigned& sense)
{
    __syncthreads();
    unsigned s = sense ^ 1u;
    sense = s;
    if (threadIdx.x == 0) {
        unsigned* sub = &g_sub[(grp * 4 + subi) * 32];
        unsigned* sup = &g_sup[grp * 32];
        unsigned* sns = &g_sns[grp * 32];
        unsigned old;
        asm volatile("atom.release.gpu.global.add.u32 %0, [%1], 1;"
                     : "=r"(old) : "l"(sub) : "memory");
        bool done = false;
        if (old == 7u) {
            unsigned so;
            asm volatile("atom.acq_rel.gpu.global.add.u32 %0, [%1], 1;"
                         : "=r"(so) : "l"(sup) : "memory");
            if (so == 3u) {
                // all 32 arrived: reset counters, then release the sense word
#pragma unroll
                for (int i = 0; i < 4; i++)
                    asm volatile("st.relaxed.gpu.global.u32 [%0], 0;"
                                 :: "l"(&g_sub[(grp * 4 + i) * 32]) : "memory");
                asm volatile("st.relaxed.gpu.global.u32 [%0], 0;"
                             :: "l"(sup) : "memory");
                asm volatile("st.release.gpu.global.u32 [%0], %1;"
                             :: "l"(sns), "r"(s) : "memory");
                done = true;
            }
        }
        if (!done) {
            unsigned v;
            do {
                asm volatile("ld.acquire.gpu.global.u32 %0, [%1];"
                             : "=r"(v) : "l"(sns) : "memory");
            } while (v != s);
        }
    }
    __syncthreads();
}

// ---------------- fused kernel: GEMM prologue + persistent recurrence ----------
// 128 CTAs x 512 threads.
// Phase 1 (512 thr): xw = A * W_ih^T + (bih+bhh). Each CTA: 16 pairs of
//   adjacent 128x128 tiles (warps 0-7 -> n-tile 2np, warps 8-15 -> 2np+1,
//   shared As). Per-thread math bitwise identical to the R8 standalone GEMM.
// Phase 2 (256 thr; warps 8-15 exit): EXACT R8 recurrence, tree-arrive barrier.
__global__ void __launch_bounds__(512, 1) lstm_fused(
    const float* __restrict__ A,      // [T,B,in] input sequence for this layer
    const float* __restrict__ Wih,    // [4H, in]
    const float* __restrict__ bih,
    const float* __restrict__ bhh,
    const float* __restrict__ wpT,    // layer's packed W_hh [k][gate][u]
    float* __restrict__ xw,           // [T][BATCH][GATES]
    float* __restrict__ hT,           // [2][NGRP][HID][16]
    float* __restrict__ ybase,        // [T][BATCH][HID]
    float* __restrict__ hs_out,
    float* __restrict__ cs_out)
{
    extern __shared__ __align__(16) float smem[];

    const int tid = threadIdx.x;

    // ================= Phase 1: GEMM =================
    {
        float* As = smem;             // [2][16][128]  4096 floats
        float* Bs = smem + 4096;      // [2][16][256]  8192 floats
        const int half = tid >> 8;    // 0/1 -> n-subtile
        const int htid = tid & 255;
        const int tm = htid >> 4;
        const int tn = htid & 15;

#define LOADT(k0, s)                                                          \
    {                                                                         \
        {   /* A: 2048 floats, 1 float4/thread */                             \
            int v  = tid;                                                     \
            int rr = v >> 2;                                                  \
            int kq = v & 3;                                                   \
            float4 av = *(const float4*)&A[(size_t)(rowA + rr) * HID + (k0) + kq * 4]; \
            As[(s) * 2048 + (kq * 4 + 0) * 128 + rr] = av.x;                  \
            As[(s) * 2048 + (kq * 4 + 1) * 128 + rr] = av.y;                  \
            As[(s) * 2048 + (kq * 4 + 2) * 128 + rr] = av.z;                  \
            As[(s) * 2048 + (kq * 4 + 3) * 128 + rr] = av.w;                  \
        }                                                                     \
        _Pragma("unroll")                                                     \
        for (int r2 = 0; r2 < 2; r2++) {  /* B: 4096 floats, 2 float4/thread */\
            int v  = tid + r2 * 512;                                          \
            int rr = v >> 2;                                                  \
            int kq = v & 3;                                                   \
            float4 wv = *(const float4*)&Wih[(size_t)(rowW + rr) * HID + (k0) + kq * 4]; \
            Bs[(s) * 4096 + (kq * 4 + 0) * 256 + rr] = wv.x;                  \
            Bs[(s) * 4096 + (kq * 4 + 1) * 256 + rr] = wv.y;                  \
            Bs[(s) * 4096 + (kq * 4 + 2) * 256 + rr] = wv.z;                  \
            Bs[(s) * 4096 + (kq * 4 + 3) * 256 + rr] = wv.w;                  \
        }                                                                     \
    }

        for (int jp = 0; jp < 16; jp++) {
            int p  = blockIdx.x * 16 + jp;
            int m  = p >> 3;                 // 0..255
            int np = p & 7;                  // 0..7
            const int rowA = m * 128;
            const int rowW = np * 256;

            unsigned long long acc2[8][4];
#pragma unroll
            for (int i = 0; i < 8; i++)
#pragma unroll
                for (int q = 0; q < 4; q++) acc2[i][q] = 0ull;

            LOADT(0, 0)

            for (int it2 = 0; it2 < 32; it2++) {
                __syncthreads();
                int s = it2 & 1;
                if (it2 + 1 < 32) LOADT((it2 + 1) * 16, s ^ 1)
#pragma unroll
                for (int kk = 0; kk < 16; kk++) {
                    float a[8];
                    const float* ar = &As[s * 2048 + kk * 128 + tm * 8];
                    float4 t0 = *(const float4*)(ar);
                    float4 t1 = *(const float4*)(ar + 4);
                    a[0]=t0.x; a[1]=t0.y; a[2]=t0.z; a[3]=t0.w;
                    a[4]=t1.x; a[5]=t1.y; a[6]=t1.z; a[7]=t1.w;
                    const float* br = &Bs[s * 4096 + kk * 256 + half * 128 + tn * 8];
                    float4 s0 = *(const float4*)(br);
                    float4 s1 = *(const float4*)(br + 4);
                    unsigned long long bp[4];
                    bp[0] = pk2(s0.x, s0.y); bp[1] = pk2(s0.z, s0.w);
                    bp[2] = pk2(s1.x, s1.y); bp[3] = pk2(s1.z, s1.w);
#pragma unroll
                    for (int i = 0; i < 8; i++) {
                        unsigned long long ai = pk2(a[i], a[i]);
#pragma unroll
                        for (int q = 0; q < 4; q++)
                            acc2[i][q] = ffma2(ai, bp[q], acc2[i][q]);
                    }
                }
            }

            int n0 = rowW + half * 128 + tn * 8;
            float bias[8];
#pragma unroll
            for (int j = 0; j < 8; j++) bias[j] = bih[n0 + j] + bhh[n0 + j];
#pragma unroll
            for (int i = 0; i < 8; i++) {
                float v[8];
#pragma unroll
                for (int q = 0; q < 4; q++) unpk2(acc2[i][q], v[2*q], v[2*q+1]);
                size_t off = (size_t)(rowA + tm * 8 + i) * GATES + n0;
                float4 o0 = make_float4(v[0] + bias[0], v[1] + bias[1],
                                        v[2] + bias[2], v[3] + bias[3]);
                float4 o1 = make_float4(v[4] + bias[4], v[5] + bias[5],
                                        v[6] + bias[6], v[7] + bias[7]);
                *(float4*)&xw[off]     = o0;
                *(float4*)&xw[off + 4] = o1;
            }
            __syncthreads();   // epilogue done before next jp reuses buffers
        }
#undef LOADT
    }

    // global barrier x2 (even -> sense word self-restores across launches)
    {
        unsigned gs = 0;
        gbar(gs);
        gbar(gs);
    }

    // ================= Phase 2: recurrence (R8-exact) =================
    float* Wsh = smem;                      // [512][64]       128 KB
    float* Hsh = smem + 32768;              // [512][20]        40 KB
    float* Psh = smem + 32768 + 10240;      // [8][64][18]      36 KB

    const int utile = blockIdx.x & 31;
    const int grp   = blockIdx.x >> 5;
    const int u0 = utile * 16;
    const int b0 = grp * 16;
    const int subi = utile >> 3;            // sub-counter index 0..3

    // W_hh slice load with all 512 threads (faster), then drop warps 8-15
    for (int i = tid; i < 512 * 64; i += 512) {
        int luu = i & 15;
        int lg  = (i >> 4) & 3;
        int lk  = i >> 6;
        Wsh[i] = wpT[(size_t)lk * GATES + lg * HID + u0 + luu];
    }
    __syncthreads();
    if (tid >= 256) return;                 // exited threads don't count in bar.sync

    const int warp = tid >> 5;
    const int lane = tid & 31;
    const int uu = tid & 15;
    const int bb = tid >> 4;
    const int gidx = (b0 + bb) * HID + u0 + uu;
    const int kbase = warp * 64;

    unsigned sense = 0;
    float c = 0.f;
    float* hTg = hT + grp * (HID * 16);

    const float* xp = xw + ((size_t)(b0 + bb)) * GATES + u0 + uu;
    float x0 = xp[0], x1 = xp[512], x2 = xp[1024], x3 = xp[1536];

#pragma unroll 1
    for (int t = 0; t < T_STEPS; t++) {
        float pre0 = x0, pre1 = x1, pre2 = x2, pre3 = x3;
        if (t > 0) {
            // ---- per-warp stage of OWN chunk: LDG.128(cg) -> STS.128 --------
            const float4* src = (const float4*)(hTg +
                (size_t)((t - 1) & 1) * NGRP * HID * 16);
            const int base4 = kbase * 4;
#pragma unroll
            for (int i = 0; i < 8; i++) {
                int idx = base4 + lane + i * 32;
                float4 v = __ldcg(src + idx);
                int k  = idx >> 2;
                int ch = idx & 3;
                *(float4*)&Hsh[k * 20 + ch * 4] = v;
            }
            __syncwarp();

            // ---- compute: rows {2l,2l+1} x 16 batches over 64 consecutive k -
            unsigned long long acc2[2][8];
#pragma unroll
            for (int r = 0; r < 2; r++)
#pragma unroll
                for (int i = 0; i < 8; i++) acc2[r][i] = 0ull;

#pragma unroll 8
            for (int j = 0; j < 64; j++) {
                int k = kbase + j;
                const float* hr = &Hsh[k * 20];
                ulonglong2 q0 = *(const ulonglong2*)(hr + 0);
                ulonglong2 q1 = *(const ulonglong2*)(hr + 4);
                ulonglong2 q2 = *(const ulonglong2*)(hr + 8);
                ulonglong2 q3 = *(const ulonglong2*)(hr + 12);
                float2 wv = *(const float2*)&Wsh[k * 64 + 2 * lane];
                unsigned long long w0 = pk2(wv.x, wv.x);
                unsigned long long w1 = pk2(wv.y, wv.y);
                acc2[0][0] = ffma2(w0, q0.x, acc2[0][0]);
                acc2[0][1] = ffma2(w0, q0.y, acc2[0][1]);
                acc2[0][2] = ffma2(w0, q1.x, acc2[0][2]);
                acc2[0][3] = ffma2(w0, q1.y, acc2[0][3]);
                acc2[0][4] = ffma2(w0, q2.x, acc2[0][4]);
                acc2[0][5] = ffma2(w0, q2.y, acc2[0][5]);
                acc2[0][6] = ffma2(w0, q3.x, acc2[0][6]);
                acc2[0][7] = ffma2(w0, q3.y, acc2[0][7]);
                acc2[1][0] = ffma2(w1, q0.x, acc2[1][0]);
                acc2[1][1] = ffma2(w1, q0.y, acc2[1][1]);
                acc2[1][2] = ffma2(w1, q1.x, acc2[1][2]);
                acc2[1][3] = ffma2(w1, q1.y, acc2[1][3]);
                acc2[1][4] = ffma2(w1, q2.x, acc2[1][4]);
                acc2[1][5] = ffma2(w1, q2.y, acc2[1][5]);
                acc2[1][6] = ffma2(w1, q3.x, acc2[1][6]);
                acc2[1][7] = ffma2(w1, q3.y, acc2[1][7]);
            }

            // ---- write partials to own region -------------------------------
#pragma unroll
            for (int r = 0; r < 2; r++) {
                int base = warp * 1152 + (2 * lane + r) * 18;
#pragma unroll
                for (int i = 0; i < 8; i++)
                    *(unsigned long long*)&Psh[base + 2 * i] = acc2[r][i];
            }
            __syncthreads();

            // ---- fixed-order reduction: chunks 0..7 ascending, + xw last ----
            float s0 = Psh[(0 * 16 + uu) * 18 + bb];
            float s1 = Psh[(1 * 16 + uu) * 18 + bb];
            float s2 = Psh[(2 * 16 + uu) * 18 + bb];
            float s3 = Psh[(3 * 16 + uu) * 18 + bb];
#pragma unroll
            for (int cc = 1; cc < 8; cc++) {
                int base = cc * 1152 + uu * 18 + bb;
                s0 += Psh[base];
                s1 += Psh[base + 16 * 18];
                s2 += Psh[base + 32 * 18];
                s3 += Psh[base + 48 * 18];
            }
            pre0 = s0 + x0; pre1 = s1 + x1;
            pre2 = s2 + x2; pre3 = s3 + x3;
        }

        {
            float i_ = pre0 >= 0.f ? 1.f : 0.f;
            float f_ = pre1 >= 0.f ? 1.f : 0.f;
            float gg = pre2 >= 0.f ? 1.f : 0.f;
            float o_ = pre3 >= 0.f ? 1.f : 0.f;

            c = c * f_ + i_ * gg;
            float h = c * o_;

            __stcg(&ybase[(size_t)t * BATCH * HID + gidx], h);
            __stcg(&hTg[(size_t)(t & 1) * NGRP * HID * 16 + (u0 + uu) * 16 + bb], h);
            if (t == T_STEPS - 1) {
                hs_out[gidx] = h;
                cs_out[gidx] = c;
            }
        }

        // prefetch xw(t+1) — DRAM latency hides under the barrier wait
        if (t + 1 < T_STEPS) {
            const float* xr = xw + ((size_t)(t + 1) * BATCH + b0 + bb) * GATES
                                 + u0 + uu;
            x0 = xr[0]; x1 = xr[512]; x2 = xr[1024]; x3 = xr[1536];
        }

        group_bar(grp, subi, sense);   // 512 flips: sense word self-restores
    }
}

// ---------------- launch --------------------------------------------------------
extern "C" void kernel_launch(void* const* d_in, const int* in_sizes, int n_in,
                              void* d_out, int out_size)
{
    (void)in_sizes; (void)n_in; (void)out_size;
    const float* x    = (const float*)d_in[0];
    const float* W_ih = (const float*)d_in[1];
    const float* W_hh = (const float*)d_in[2];
    const float* b_ih = (const float*)d_in[3];
    const float* b_hh = (const float*)d_in[4];
    float* out = (float*)d_out;

    float *xw, *seq1, *hT, *wpT;
    cudaGetSymbolAddress((void**)&xw,   g_xw);
    cudaGetSymbolAddress((void**)&seq1, g_seq1);
    cudaGetSymbolAddress((void**)&hT,   g_hT);
    cudaGetSymbolAddress((void**)&wpT,  g_wpT);

    const int SMEM_BYTES = (32768 + 10240 + 9216) * 4;   // 208896
    cudaFuncSetAttribute(lstm_fused, cudaFuncAttributeMaxDynamicSharedMemorySize,
                         SMEM_BYTES);

    pack_whh<<<(NLAYER * HID * GATES) / 256, 256>>>(W_hh);

    const size_t TBH = (size_t)T_STEPS * BATCH * HID;

    for (int l = 0; l < NLAYER; l++) {
        const float* Ain = (l == 0) ? x : seq1;
        float* ybase = (l == 0) ? seq1 : out;
        float* hs = out + TBH + (size_t)l * BATCH * HID;
        float* cs = out + TBH + (size_t)NLAYER * BATCH * HID + (size_t)l * BATCH * HID;

        lstm_fused<<<NB, 512, SMEM_BYTES>>>(
            Ain,
            W_ih + (size_t)l * GATES * HID,
            b_ih + (size_t)l * GATES,
            b_hh + (size_t)l * GATES,
            wpT + (size_t)l * HID * GATES,
            xw, hT, ybase, hs, cs);
    }
}

// round 11
// speedup vs baseline: 1.2020x; 1.1435x over previous
#include <cuda_runtime.h>
#include <cstddef>

#define T_STEPS 512
#define BATCH   64
#define HID     512
#define GATES   2048
#define NLAYER  2
#define MROWS   (T_STEPS * BATCH)   // 32768
#define NB      128                 // persistent CTAs
#define NGRP    4                   // independent batch groups
#define GRP_CTAS 32                 // CTAs per group

// ---------------- device scratch (static allocation — allowed) ----------------
__device__ float g_xw[(size_t)MROWS * GATES];            // 256 MB input projection
__device__ float g_seq1[(size_t)T_STEPS * BATCH * HID];  // 64 MB layer-0 output
__device__ float g_hT[2 * NGRP * HID * 16];              // transposed h [buf][grp][u][b]
__device__ float g_wpT[(size_t)NLAYER * HID * GATES];    // packed W_hh [l][k][gate][u]

// barrier state, one 128B line per group
__device__ unsigned g_cnt2[NGRP * 32];
__device__ unsigned g_sns2[NGRP * 32];

// ---------------- f32x2 helpers ------------------------------------------------
__device__ __forceinline__ unsigned long long pk2(float lo, float hi) {
    unsigned long long r;
    asm("mov.b64 %0, {%1, %2};" : "=l"(r) : "f"(lo), "f"(hi));
    return r;
}
__device__ __forceinline__ unsigned long long ffma2(
    unsigned long long a, unsigned long long b, unsigned long long c) {
    unsigned long long d;
    asm("fma.rn.f32x2 %0, %1, %2, %3;" : "=l"(d) : "l"(a), "l"(b), "l"(c));
    return d;
}
__device__ __forceinline__ void unpk2(unsigned long long v, float& lo, float& hi) {
    asm("mov.b64 {%0, %1}, %2;" : "=f"(lo), "=f"(hi) : "l"(v));
}

// ---------------- pack W_hh into [k][gate][u] ----------------------------------
__global__ void pack_whh(const float* __restrict__ W_hh)
{
    int idx = blockIdx.x * 256 + threadIdx.x;
    int l = idx / (HID * GATES);
    int r = idx - l * (HID * GATES);
    int k    = r >> 11;
    int q    = r & 2047;
    int gate = q >> 9;
    int u    = q & 511;
    g_wpT[idx] = W_hh[((size_t)l * GATES + gate * HID + u) * HID + k];
}

// ---------------- SGEMM: C[M,2048] = A[M,512]*W[2048,512]^T + (bih+bhh) --------
// Double-buffered, k-stage depth 32 (dynamic smem 64 KB): half the syncthreads
// of the R8 version; per-thread k-accumulation order identical (ascending k).
__global__ void __launch_bounds__(256) gemm_bias(
    const float* __restrict__ A,
    const float* __restrict__ W,
    const float* __restrict__ bih,
    const float* __restrict__ bhh,
    float* __restrict__ C)
{
    extern __shared__ __align__(16) float gsm[];
    float* As = gsm;            // [2][32][128]  (8192 floats)
    float* Bs = gsm + 8192;     // [2][32][128]

    int tid = threadIdx.x;
    int bx = blockIdx.x;
    int by = blockIdx.y;
    int tm = tid >> 4;
    int tn = tid & 15;

    unsigned long long acc2[8][4];
#pragma unroll
    for (int i = 0; i < 8; i++)
#pragma unroll
        for (int p = 0; p < 4; p++) acc2[i][p] = 0ull;

    const int rowA = by * 128;
    const int rowW = bx * 128;

    // stage loader: 32 k x 128 rows each matrix; 4 float4/thread/matrix
#define LOAD_TILE(k0, s)                                                      \
    {                                                                         \
        _Pragma("unroll")                                                     \
        for (int r = 0; r < 4; r++) {                                         \
            int v  = tid + r * 256;          /* 0..1023 */                    \
            int rr = v >> 3;                 /* row 0..127 */                 \
            int kq = v & 7;                  /* k-quad 0..7 */                \
            float4 av = *(const float4*)&A[(size_t)(rowA + rr) * HID + (k0) + kq * 4]; \
            As[(s) * 4096 + (kq * 4 + 0) * 128 + rr] = av.x;                  \
            As[(s) * 4096 + (kq * 4 + 1) * 128 + rr] = av.y;                  \
            As[(s) * 4096 + (kq * 4 + 2) * 128 + rr] = av.z;                  \
            As[(s) * 4096 + (kq * 4 + 3) * 128 + rr] = av.w;                  \
            float4 wv = *(const float4*)&W[(size_t)(rowW + rr) * HID + (k0) + kq * 4]; \
            Bs[(s) * 4096 + (kq * 4 + 0) * 128 + rr] = wv.x;                  \
            Bs[(s) * 4096 + (kq * 4 + 1) * 128 + rr] = wv.y;                  \
            Bs[(s) * 4096 + (kq * 4 + 2) * 128 + rr] = wv.z;                  \
            Bs[(s) * 4096 + (kq * 4 + 3) * 128 + rr] = wv.w;                  \
        }                                                                     \
    }

    LOAD_TILE(0, 0)

    for (int it = 0; it < 16; it++) {
        __syncthreads();
        int s = it & 1;
        if (it + 1 < 16) LOAD_TILE((it + 1) * 32, s ^ 1)
#pragma unroll
        for (int kk = 0; kk < 32; kk++) {
            float a[8];
            const float* ar = &As[s * 4096 + kk * 128 + tm * 8];
            float4 t0 = *(const float4*)(ar);
            float4 t1 = *(const float4*)(ar + 4);
            a[0]=t0.x; a[1]=t0.y; a[2]=t0.z; a[3]=t0.w;
            a[4]=t1.x; a[5]=t1.y; a[6]=t1.z; a[7]=t1.w;
            const float* br = &Bs[s * 4096 + kk * 128 + tn * 8];
            float4 s0 = *(const float4*)(br);
            float4 s1 = *(const float4*)(br + 4);
            unsigned long long bp[4];
            bp[0] = pk2(s0.x, s0.y); bp[1] = pk2(s0.z, s0.w);
            bp[2] = pk2(s1.x, s1.y); bp[3] = pk2(s1.z, s1.w);
#pragma unroll
            for (int i = 0; i < 8; i++) {
                unsigned long long ai = pk2(a[i], a[i]);
#pragma unroll
                for (int p = 0; p < 4; p++)
                    acc2[i][p] = ffma2(ai, bp[p], acc2[i][p]);
            }
        }
    }
#undef LOAD_TILE

    int n0 = rowW + tn * 8;
    float bias[8];
#pragma unroll
    for (int j = 0; j < 8; j++) bias[j] = bih[n0 + j] + bhh[n0 + j];
#pragma unroll
    for (int i = 0; i < 8; i++) {
        float v[8];
#pragma unroll
        for (int p = 0; p < 4; p++) unpk2(acc2[i][p], v[2*p], v[2*p+1]);
        size_t off = (size_t)(rowA + tm * 8 + i) * GATES + n0;
        float4 o0 = make_float4(v[0] + bias[0], v[1] + bias[1],
                                v[2] + bias[2], v[3] + bias[3]);
        float4 o1 = make_float4(v[4] + bias[4], v[5] + bias[5],
                                v[6] + bias[6], v[7] + bias[7]);
        *(float4*)&C[off]     = o0;
        *(float4*)&C[off + 4] = o1;
    }
}

// ---------------- persistent recurrence ----------------------------------------
// R8-exact compute; barrier split into arrive / overlap / wait so the y-store
// and xw prefetch hide under other CTAs' arrivals.
__global__ void __launch_bounds__(256, 1) lstm_seq(
    const float* __restrict__ wpT,    // layer's packed W_hh [k][gate][u]
    const float* __restrict__ xw,     // [T][BATCH][GATES]
    float* __restrict__ hT,           // [2][NGRP][HID][16]
    float* __restrict__ ybase,        // [T][BATCH][HID]
    float* __restrict__ hs_out,
    float* __restrict__ cs_out)
{
    extern __shared__ __align__(16) float smem[];
    float* Wsh = smem;                      // [512][64]       128 KB
    float* Hsh = smem + 32768;              // [512][20]        40 KB
    float* Psh = smem + 32768 + 10240;      // [8][64][18]      36 KB

    const int tid  = threadIdx.x;
    const int warp = tid >> 5;          // k-chunk 0..7
    const int lane = tid & 31;
    const int utile = blockIdx.x & 31;
    const int grp   = blockIdx.x >> 5;
    const int u0 = utile * 16;
    const int b0 = grp * 16;
    const int uu = tid & 15;            // update role
    const int bb = tid >> 4;            // batch 0..15
    const int gidx = (b0 + bb) * HID + u0 + uu;
    const int kbase = warp * 64;

    unsigned* cnt = &g_cnt2[grp * 32];
    unsigned* sns = &g_sns2[grp * 32];

    // ---- load this CTA's W_hh slice into smem once: Wsh[k*64 + g*16 + u] ----
    for (int i = tid; i < 512 * 64; i += 256) {
        int luu = i & 15;
        int lg  = (i >> 4) & 3;
        int lk  = i >> 6;
        Wsh[i] = wpT[(size_t)lk * GATES + lg * HID + u0 + luu];
    }
    __syncthreads();

    unsigned sense = 0;
    float c = 0.f;
    float* hTg = hT + grp * (HID * 16);

    const float* xp = xw + ((size_t)(b0 + bb)) * GATES + u0 + uu;
    float x0 = xp[0], x1 = xp[512], x2 = xp[1024], x3 = xp[1536];

#pragma unroll 1
    for (int t = 0; t < T_STEPS; t++) {
        float pre0 = x0, pre1 = x1, pre2 = x2, pre3 = x3;
        if (t > 0) {
            // ---- per-warp stage of OWN chunk: LDG.128(cg) -> STS.128 --------
            const float4* src = (const float4*)(hTg +
                (size_t)((t - 1) & 1) * NGRP * HID * 16);
            const int base4 = kbase * 4;
#pragma unroll
            for (int i = 0; i < 8; i++) {
                int idx = base4 + lane + i * 32;
                float4 v = __ldcg(src + idx);
                int k  = idx >> 2;
                int ch = idx & 3;
                *(float4*)&Hsh[k * 20 + ch * 4] = v;
            }
            __syncwarp();

            // ---- compute: rows {2l,2l+1} x 16 batches over 64 consecutive k -
            unsigned long long acc2[2][8];
#pragma unroll
            for (int r = 0; r < 2; r++)
#pragma unroll
                for (int i = 0; i < 8; i++) acc2[r][i] = 0ull;

#pragma unroll 8
            for (int j = 0; j < 64; j++) {
                int k = kbase + j;
                const float* hr = &Hsh[k * 20];
                ulonglong2 q0 = *(const ulonglong2*)(hr + 0);
                ulonglong2 q1 = *(const ulonglong2*)(hr + 4);
                ulonglong2 q2 = *(const ulonglong2*)(hr + 8);
                ulonglong2 q3 = *(const ulonglong2*)(hr + 12);
                float2 wv = *(const float2*)&Wsh[k * 64 + 2 * lane];
                unsigned long long w0 = pk2(wv.x, wv.x);
                unsigned long long w1 = pk2(wv.y, wv.y);
                acc2[0][0] = ffma2(w0, q0.x, acc2[0][0]);
                acc2[0][1] = ffma2(w0, q0.y, acc2[0][1]);
                acc2[0][2] = ffma2(w0, q1.x, acc2[0][2]);
                acc2[0][3] = ffma2(w0, q1.y, acc2[0][3]);
                acc2[0][4] = ffma2(w0, q2.x, acc2[0][4]);
                acc2[0][5] = ffma2(w0, q2.y, acc2[0][5]);
                acc2[0][6] = ffma2(w0, q3.x, acc2[0][6]);
                acc2[0][7] = ffma2(w0, q3.y, acc2[0][7]);
                acc2[1][0] = ffma2(w1, q0.x, acc2[1][0]);
                acc2[1][1] = ffma2(w1, q0.y, acc2[1][1]);
                acc2[1][2] = ffma2(w1, q1.x, acc2[1][2]);
                acc2[1][3] = ffma2(w1, q1.y, acc2[1][3]);
                acc2[1][4] = ffma2(w1, q2.x, acc2[1][4]);
                acc2[1][5] = ffma2(w1, q2.y, acc2[1][5]);
                acc2[1][6] = ffma2(w1, q3.x, acc2[1][6]);
                acc2[1][7] = ffma2(w1, q3.y, acc2[1][7]);
            }

            // ---- write partials to own region -------------------------------
#pragma unroll
            for (int r = 0; r < 2; r++) {
                int base = warp * 1152 + (2 * lane + r) * 18;
#pragma unroll
                for (int i = 0; i < 8; i++)
                    *(unsigned long long*)&Psh[base + 2 * i] = acc2[r][i];
            }
            __syncthreads();

            // ---- fixed-order reduction: chunks 0..7 ascending, + xw last ----
            float s0 = Psh[(0 * 16 + uu) * 18 + bb];
            float s1 = Psh[(1 * 16 + uu) * 18 + bb];
            float s2 = Psh[(2 * 16 + uu) * 18 + bb];
            float s3 = Psh[(3 * 16 + uu) * 18 + bb];
#pragma unroll
            for (int cc = 1; cc < 8; cc++) {
                int base = cc * 1152 + uu * 18 + bb;
                s0 += Psh[base];
                s1 += Psh[base + 16 * 18];
                s2 += Psh[base + 32 * 18];
                s3 += Psh[base + 48 * 18];
            }
            pre0 = s0 + x0; pre1 = s1 + x1;
            pre2 = s2 + x2; pre3 = s3 + x3;
        }

        float i_ = pre0 >= 0.f ? 1.f : 0.f;
        float f_ = pre1 >= 0.f ? 1.f : 0.f;
        float gg = pre2 >= 0.f ? 1.f : 0.f;
        float o_ = pre3 >= 0.f ? 1.f : 0.f;

        c = c * f_ + i_ * gg;
        float h = c * o_;

        // ---- h store, then EARLY barrier arrive -----------------------------
        __stcg(&hTg[(size_t)(t & 1) * NGRP * HID * 16 + (u0 + uu) * 16 + bb], h);
        if (t == T_STEPS - 1) {
            hs_out[gidx] = h;
            cs_out[gidx] = c;
        }
        unsigned s = sense ^ 1u;
        sense = s;
        __syncthreads();                 // all h(t) stores issued CTA-wide
        if (tid == 0) {
            unsigned old;
            asm volatile("atom.acq_rel.gpu.global.add.u32 %0, [%1], 1;"
                         : "=r"(old) : "l"(cnt) : "memory");
            if (old == GRP_CTAS - 1u) {
                asm volatile("st.relaxed.gpu.global.u32 [%0], 0;"
                             :: "l"(cnt) : "memory");
                asm volatile("st.release.gpu.global.u32 [%0], %1;"
                             :: "l"(sns), "r"(s) : "memory");
            }
        }

        // ---- overlap window: y store + xw(t+1) prefetch ---------------------
        __stcg(&ybase[(size_t)t * BATCH * HID + gidx], h);
        if (t + 1 < T_STEPS) {
            const float* xr = xw + ((size_t)(t + 1) * BATCH + b0 + bb) * GATES
                                 + u0 + uu;
            x0 = xr[0]; x1 = xr[512]; x2 = xr[1024]; x3 = xr[1536];
        }

        // ---- wait -----------------------------------------------------------
        if (tid == 0) {
            unsigned v;
            do {
                asm volatile("ld.acquire.gpu.global.u32 %0, [%1];"
                             : "=r"(v) : "l"(sns) : "memory");
            } while (v != s);
        }
        __syncthreads();                 // 512 flips: sense self-restores
    }
}

// ---------------- launch --------------------------------------------------------
extern "C" void kernel_launch(void* const* d_in, const int* in_sizes, int n_in,
                              void* d_out, int out_size)
{
    (void)in_sizes; (void)n_in; (void)out_size;
    const float* x    = (const float*)d_in[0];
    const float* W_ih = (const float*)d_in[1];
    const float* W_hh = (const float*)d_in[2];
    const float* b_ih = (const float*)d_in[3];
    const float* b_hh = (const float*)d_in[4];
    float* out = (float*)d_out;

    float *xw, *seq1, *hT, *wpT;
    cudaGetSymbolAddress((void**)&xw,   g_xw);
    cudaGetSymbolAddress((void**)&seq1, g_seq1);
    cudaGetSymbolAddress((void**)&hT,   g_hT);
    cudaGetSymbolAddress((void**)&wpT,  g_wpT);

    const int GEMM_SMEM = 2 * 8192 * 4;                  // 65536
    cudaFuncSetAttribute(gemm_bias, cudaFuncAttributeMaxDynamicSharedMemorySize,
                         GEMM_SMEM);
    const int SMEM_BYTES = (32768 + 10240 + 9216) * 4;   // 208896
    cudaFuncSetAttribute(lstm_seq, cudaFuncAttributeMaxDynamicSharedMemorySize,
                         SMEM_BYTES);

    pack_whh<<<(NLAYER * HID * GATES) / 256, 256>>>(W_hh);

    const size_t TBH = (size_t)T_STEPS * BATCH * HID;

    for (int l = 0; l < NLAYER; l++) {
        const float* A = (l == 0) ? x : seq1;
        gemm_bias<<<dim3(GATES / 128, MROWS / 128), 256, GEMM_SMEM>>>(
            A, W_ih + (size_t)l * GATES * HID,
            b_ih + (size_t)l * GATES, b_hh + (size_t)l * GATES, xw);

        float* ybase = (l == 0) ? seq1 : out;
        float* hs = out + TBH + (size_t)l * BATCH * HID;
        float* cs = out + TBH + (size_t)NLAYER * BATCH * HID + (size_t)l * BATCH * HID;

        lstm_seq<<<NB, 256, SMEM_BYTES>>>(wpT + (size_t)l * HID * GATES,
                                          xw, hT, ybase, hs, cs);
    }
}

// round 13
// speedup vs baseline: 1.2245x; 1.0187x over previous
#include <cuda_runtime.h>
#include <cstddef>

#define T_STEPS 512
#define BATCH   64
#define HID     512
#define GATES   2048
#define NLAYER  2
#define MROWS   (T_STEPS * BATCH)   // 32768
#define NB      128                 // persistent CTAs
#define NGRP    4                   // independent batch groups
#define GRP_CTAS 32                 // CTAs per group

// ---------------- device scratch (static allocation — allowed) ----------------
__device__ float g_xw[(size_t)MROWS * GATES];            // 256 MB input projection
__device__ float g_seq1[(size_t)T_STEPS * BATCH * HID];  // 64 MB layer-0 output
__device__ float g_hT[2 * NGRP * HID * 16];              // transposed h [buf][grp][u][b]
__device__ float g_wpT[(size_t)NLAYER * HID * GATES];    // packed W_hh [l][k][gate][u]

// barrier state, one 128B line per group
__device__ unsigned g_cnt2[NGRP * 32];
__device__ unsigned g_sns2[NGRP * 32];

// ---------------- f32x2 helpers ------------------------------------------------
__device__ __forceinline__ unsigned long long pk2(float lo, float hi) {
    unsigned long long r;
    asm("mov.b64 %0, {%1, %2};" : "=l"(r) : "f"(lo), "f"(hi));
    return r;
}
__device__ __forceinline__ unsigned long long ffma2(
    unsigned long long a, unsigned long long b, unsigned long long c) {
    unsigned long long d;
    asm("fma.rn.f32x2 %0, %1, %2, %3;" : "=l"(d) : "l"(a), "l"(b), "l"(c));
    return d;
}
__device__ __forceinline__ void unpk2(unsigned long long v, float& lo, float& hi) {
    asm("mov.b64 {%0, %1}, %2;" : "=f"(lo), "=f"(hi) : "l"(v));
}

// ---------------- pack W_hh into [k][gate][u] ----------------------------------
__global__ void pack_whh(const float* __restrict__ W_hh)
{
    int idx = blockIdx.x * 256 + threadIdx.x;
    int l = idx / (HID * GATES);
    int r = idx - l * (HID * GATES);
    int k    = r >> 11;
    int q    = r & 2047;
    int gate = q >> 9;
    int u    = q & 511;
    g_wpT[idx] = W_hh[((size_t)l * GATES + gate * HID + u) * HID + k];
}

// ---------------- SGEMM: C[M,2048] = A[M,512]*W[2048,512]^T + (bih+bhh) --------
// 128x64 tile, 8x4 per-thread microtile, double-buffered 16-k stages,
// 3 CTAs/SM. Per-output k-chain order identical to R8 -> bit-identical C.
__global__ void __launch_bounds__(256, 3) gemm_bias(
    const float* __restrict__ A,
    const float* __restrict__ W,
    const float* __restrict__ bih,
    const float* __restrict__ bhh,
    float* __restrict__ C)
{
    __shared__ __align__(16) float As[2][16][128];
    __shared__ __align__(16) float Bs[2][16][64];

    int tid = threadIdx.x;
    int bx = blockIdx.x;           // n tile (0..31), 64 wide
    int by = blockIdx.y;           // m tile (0..255)
    int tm = tid >> 4;             // 0..15
    int tn = tid & 15;             // 0..15

    unsigned long long acc2[8][2];
#pragma unroll
    for (int i = 0; i < 8; i++)
#pragma unroll
        for (int p = 0; p < 2; p++) acc2[i][p] = 0ull;

    const int rowA = by * 128;
    const int rowW = bx * 64;

#define LOAD_TILE(k0, s)                                                      \
    {                                                                         \
        _Pragma("unroll")                                                     \
        for (int r = 0; r < 2; r++) {                                         \
            int v  = tid + r * 256;                                           \
            int rr = v >> 2;                                                  \
            int kq = v & 3;                                                   \
            float4 av = *(const float4*)&A[(size_t)(rowA + rr) * HID + (k0) + kq * 4]; \
            As[s][kq * 4 + 0][rr] = av.x; As[s][kq * 4 + 1][rr] = av.y;       \
            As[s][kq * 4 + 2][rr] = av.z; As[s][kq * 4 + 3][rr] = av.w;       \
        }                                                                     \
        {                                                                     \
            int v  = tid;                                                     \
            int rr = v >> 2;                                                  \
            int kq = v & 3;                                                   \
            float4 wv = *(const float4*)&W[(size_t)(rowW + rr) * HID + (k0) + kq * 4]; \
            Bs[s][kq * 4 + 0][rr] = wv.x; Bs[s][kq * 4 + 1][rr] = wv.y;       \
            Bs[s][kq * 4 + 2][rr] = wv.z; Bs[s][kq * 4 + 3][rr] = wv.w;       \
        }                                                                     \
    }

    LOAD_TILE(0, 0)

    for (int it = 0; it < 32; it++) {
        __syncthreads();
        int s = it & 1;
        if (it + 1 < 32) LOAD_TILE((it + 1) * 16, s ^ 1)
#pragma unroll
        for (int kk = 0; kk < 16; kk++) {
            float a[8];
            float4 t0 = *(const float4*)&As[s][kk][tm * 8];
            float4 t1 = *(const float4*)&As[s][kk][tm * 8 + 4];
            a[0]=t0.x; a[1]=t0.y; a[2]=t0.z; a[3]=t0.w;
            a[4]=t1.x; a[5]=t1.y; a[6]=t1.z; a[7]=t1.w;
            float4 s0 = *(const float4*)&Bs[s][kk][tn * 4];
            unsigned long long bp[2];
            bp[0] = pk2(s0.x, s0.y); bp[1] = pk2(s0.z, s0.w);
#pragma unroll
            for (int i = 0; i < 8; i++) {
                unsigned long long ai = pk2(a[i], a[i]);
                acc2[i][0] = ffma2(ai, bp[0], acc2[i][0]);
                acc2[i][1] = ffma2(ai, bp[1], acc2[i][1]);
            }
        }
    }
#undef LOAD_TILE

    int n0 = rowW + tn * 4;
    float bias[4];
#pragma unroll
    for (int j = 0; j < 4; j++) bias[j] = bih[n0 + j] + bhh[n0 + j];
#pragma unroll
    for (int i = 0; i < 8; i++) {
        float v[4];
        unpk2(acc2[i][0], v[0], v[1]);
        unpk2(acc2[i][1], v[2], v[3]);
        size_t off = (size_t)(rowA + tm * 8 + i) * GATES + n0;
        float4 o0 = make_float4(v[0] + bias[0], v[1] + bias[1],
                                v[2] + bias[2], v[3] + bias[3]);
        *(float4*)&C[off] = o0;
    }
}

// ---------------- persistent recurrence ----------------------------------------
// R8-exact compute; barrier split into arrive / overlap / wait so the y-store
// and xw prefetch hide under other CTAs' arrivals.
__global__ void __launch_bounds__(256, 1) lstm_seq(
    const float* __restrict__ wpT,    // layer's packed W_hh [k][gate][u]
    const float* __restrict__ xw,     // [T][BATCH][GATES]
    float* __restrict__ hT,           // [2][NGRP][HID][16]
    float* __restrict__ ybase,        // [T][BATCH][HID]
    float* __restrict__ hs_out,
    float* __restrict__ cs_out)
{
    extern __shared__ __align__(16) float smem[];
    float* Wsh = smem;                      // [512][64]       128 KB
    float* Hsh = smem + 32768;              // [512][20]        40 KB
    float* Psh = smem + 32768 + 10240;      // [8][64][18]      36 KB

    const int tid  = threadIdx.x;
    const int warp = tid >> 5;          // k-chunk 0..7
    const int lane = tid & 31;
    const int utile = blockIdx.x & 31;
    const int grp   = blockIdx.x >> 5;
    const int u0 = utile * 16;
    const int b0 = grp * 16;
    const int uu = tid & 15;            // update role
    const int bb = tid >> 4;            // batch 0..15
    const int gidx = (b0 + bb) * HID + u0 + uu;
    const int kbase = warp * 64;

    unsigned* cnt = &g_cnt2[grp * 32];
    unsigned* sns = &g_sns2[grp * 32];

    // ---- load this CTA's W_hh slice into smem once: Wsh[k*64 + g*16 + u] ----
    for (int i = tid; i < 512 * 64; i += 256) {
        int luu = i & 15;
        int lg  = (i >> 4) & 3;
        int lk  = i >> 6;
        Wsh[i] = wpT[(size_t)lk * GATES + lg * HID + u0 + luu];
    }
    __syncthreads();

    unsigned sense = 0;
    float c = 0.f;
    float* hTg = hT + grp * (HID * 16);

    const float* xp = xw + ((size_t)(b0 + bb)) * GATES + u0 + uu;
    float x0 = xp[0], x1 = xp[512], x2 = xp[1024], x3 = xp[1536];

#pragma unroll 1
    for (int t = 0; t < T_STEPS; t++) {
        float pre0 = x0, pre1 = x1, pre2 = x2, pre3 = x3;
        if (t > 0) {
            // ---- per-warp stage of OWN chunk: LDG.128(cg) -> STS.128 --------
            const float4* src = (const float4*)(hTg +
                (size_t)((t - 1) & 1) * NGRP * HID * 16);
            const int base4 = kbase * 4;
#pragma unroll
            for (int i = 0; i < 8; i++) {
                int idx = base4 + lane + i * 32;
                float4 v = __ldcg(src + idx);
                int k  = idx >> 2;
                int ch = idx & 3;
                *(float4*)&Hsh[k * 20 + ch * 4] = v;
            }
            __syncwarp();

            // ---- compute: rows {2l,2l+1} x 16 batches over 64 consecutive k -
            unsigned long long acc2[2][8];
#pragma unroll
            for (int r = 0; r < 2; r++)
#pragma unroll
                for (int i = 0; i < 8; i++) acc2[r][i] = 0ull;

#pragma unroll 8
            for (int j = 0; j < 64; j++) {
                int k = kbase + j;
                const float* hr = &Hsh[k * 20];
                ulonglong2 q0 = *(const ulonglong2*)(hr + 0);
                ulonglong2 q1 = *(const ulonglong2*)(hr + 4);
                ulonglong2 q2 = *(const ulonglong2*)(hr + 8);
                ulonglong2 q3 = *(const ulonglong2*)(hr + 12);
                float2 wv = *(const float2*)&Wsh[k * 64 + 2 * lane];
                unsigned long long w0 = pk2(wv.x, wv.x);
                unsigned long long w1 = pk2(wv.y, wv.y);
                acc2[0][0] = ffma2(w0, q0.x, acc2[0][0]);
                acc2[0][1] = ffma2(w0, q0.y, acc2[0][1]);
                acc2[0][2] = ffma2(w0, q1.x, acc2[0][2]);
                acc2[0][3] = ffma2(w0, q1.y, acc2[0][3]);
                acc2[0][4] = ffma2(w0, q2.x, acc2[0][4]);
                acc2[0][5] = ffma2(w0, q2.y, acc2[0][5]);
                acc2[0][6] = ffma2(w0, q3.x, acc2[0][6]);
                acc2[0][7] = ffma2(w0, q3.y, acc2[0][7]);
                acc2[1][0] = ffma2(w1, q0.x, acc2[1][0]);
                acc2[1][1] = ffma2(w1, q0.y, acc2[1][1]);
                acc2[1][2] = ffma2(w1, q1.x, acc2[1][2]);
                acc2[1][3] = ffma2(w1, q1.y, acc2[1][3]);
                acc2[1][4] = ffma2(w1, q2.x, acc2[1][4]);
                acc2[1][5] = ffma2(w1, q2.y, acc2[1][5]);
                acc2[1][6] = ffma2(w1, q3.x, acc2[1][6]);
                acc2[1][7] = ffma2(w1, q3.y, acc2[1][7]);
            }

            // ---- write partials to own region -------------------------------
#pragma unroll
            for (int r = 0; r < 2; r++) {
                int base = warp * 1152 + (2 * lane + r) * 18;
#pragma unroll
                for (int i = 0; i < 8; i++)
                    *(unsigned long long*)&Psh[base + 2 * i] = acc2[r][i];
            }
            __syncthreads();

            // ---- fixed-order reduction: chunks 0..7 ascending, + xw last ----
            float s0 = Psh[(0 * 16 + uu) * 18 + bb];
            float s1 = Psh[(1 * 16 + uu) * 18 + bb];
            float s2 = Psh[(2 * 16 + uu) * 18 + bb];
            float s3 = Psh[(3 * 16 + uu) * 18 + bb];
#pragma unroll
            for (int cc = 1; cc < 8; cc++) {
                int base = cc * 1152 + uu * 18 + bb;
                s0 += Psh[base];
                s1 += Psh[base + 16 * 18];
                s2 += Psh[base + 32 * 18];
                s3 += Psh[base + 48 * 18];
            }
            pre0 = s0 + x0; pre1 = s1 + x1;
            pre2 = s2 + x2; pre3 = s3 + x3;
        }

        float i_ = pre0 >= 0.f ? 1.f : 0.f;
        float f_ = pre1 >= 0.f ? 1.f : 0.f;
        float gg = pre2 >= 0.f ? 1.f : 0.f;
        float o_ = pre3 >= 0.f ? 1.f : 0.f;

        c = c * f_ + i_ * gg;
        float h = c * o_;

        // ---- h store, then EARLY barrier arrive -----------------------------
        __stcg(&hTg[(size_t)(t & 1) * NGRP * HID * 16 + (u0 + uu) * 16 + bb], h);
        if (t == T_STEPS - 1) {
            hs_out[gidx] = h;
            cs_out[gidx] = c;
        }
        unsigned s = sense ^ 1u;
        sense = s;
        __syncthreads();                 // all h(t) stores issued CTA-wide
        if (tid == 0) {
            unsigned old;
            asm volatile("atom.acq_rel.gpu.global.add.u32 %0, [%1], 1;"
                         : "=r"(old) : "l"(cnt) : "memory");
            if (old == GRP_CTAS - 1u) {
                asm volatile("st.relaxed.gpu.global.u32 [%0], 0;"
                             :: "l"(cnt) : "memory");
                asm volatile("st.release.gpu.global.u32 [%0], %1;"
                             :: "l"(sns), "r"(s) : "memory");
            }
        }

        // ---- overlap window: y store + xw(t+1) prefetch ---------------------
        __stcg(&ybase[(size_t)t * BATCH * HID + gidx], h);
        if (t + 1 < T_STEPS) {
            const float* xr = xw + ((size_t)(t + 1) * BATCH + b0 + bb) * GATES
                                 + u0 + uu;
            x0 = xr[0]; x1 = xr[512]; x2 = xr[1024]; x3 = xr[1536];
        }

        // ---- wait -----------------------------------------------------------
        if (tid == 0) {
            unsigned v;
            do {
                asm volatile("ld.acquire.gpu.global.u32 %0, [%1];"
                             : "=r"(v) : "l"(sns) : "memory");
            } while (v != s);
        }
        __syncthreads();                 // 512 flips: sense self-restores
    }
}

// ---------------- launch --------------------------------------------------------
extern "C" void kernel_launch(void* const* d_in, const int* in_sizes, int n_in,
                              void* d_out, int out_size)
{
    (void)in_sizes; (void)n_in; (void)out_size;
    const float* x    = (const float*)d_in[0];
    const float* W_ih = (const float*)d_in[1];
    const float* W_hh = (const float*)d_in[2];
    const float* b_ih = (const float*)d_in[3];
    const float* b_hh = (const float*)d_in[4];
    float* out = (float*)d_out;

    float *xw, *seq1, *hT, *wpT;
    cudaGetSymbolAddress((void**)&xw,   g_xw);
    cudaGetSymbolAddress((void**)&seq1, g_seq1);
    cudaGetSymbolAddress((void**)&hT,   g_hT);
    cudaGetSymbolAddress((void**)&wpT,  g_wpT);

    const int SMEM_BYTES = (32768 + 10240 + 9216) * 4;   // 208896
    cudaFuncSetAttribute(lstm_seq, cudaFuncAttributeMaxDynamicSharedMemorySize,
                         SMEM_BYTES);

    pack_whh<<<(NLAYER * HID * GATES) / 256, 256>>>(W_hh);

    const size_t TBH = (size_t)T_STEPS * BATCH * HID;

    for (int l = 0; l < NLAYER; l++) {
        const float* A = (l == 0) ? x : seq1;
        gemm_bias<<<dim3(GATES / 64, MROWS / 128), 256>>>(
            A, W_ih + (size_t)l * GATES * HID,
            b_ih + (size_t)l * GATES, b_hh + (size_t)l * GATES, xw);

        float* ybase = (l == 0) ? seq1 : out;
        float* hs = out + TBH + (size_t)l * BATCH * HID;
        float* cs = out + TBH + (size_t)NLAYER * BATCH * HID + (size_t)l * BATCH * HID;

        lstm_seq<<<NB, 256, SMEM_BYTES>>>(wpT + (size_t)l * HID * GATES,
                                          xw, hT, ybase, hs, cs);
    }
}